// round 7
// baseline (speedup 1.0000x reference)
#include <cuda_runtime.h>
#include <cuda_bf16.h>

#define KS 7
#define KK 49
#define TPB 128

typedef unsigned long long u64;

// ---- packed f32x2 helpers (sm_103a FFMA2/FMUL2) ----
__device__ __forceinline__ u64 pk2(float lo, float hi) {
    u64 r; asm("mov.b64 %0, {%1, %2};" : "=l"(r) : "f"(lo), "f"(hi)); return r;
}
__device__ __forceinline__ void unpk2(u64 a, float& lo, float& hi) {
    asm("mov.b64 {%0, %1}, %2;" : "=f"(lo), "=f"(hi) : "l"(a));
}
__device__ __forceinline__ u64 fma2(u64 a, u64 b, u64 c) {
    u64 d; asm("fma.rn.f32x2 %0, %1, %2, %3;" : "=l"(d) : "l"(a), "l"(b), "l"(c)); return d;
}
__device__ __forceinline__ u64 mul2(u64 a, u64 b) {
    u64 d; asm("mul.rn.f32x2 %0, %1, %2;" : "=l"(d) : "l"(a), "l"(b)); return d;
}

// Keys bicubic (a=-0.5), branch-free: cubic(x) = u^2(1-2u) + v^2(4v-2),
// u = sat(1-|x|), v = sat(1-|x|/2). C1-continuous, zero for |x|>=2.
__device__ __forceinline__ float cubic_w(float x) {
    float ax = fabsf(x);
    float u = __saturatef(1.0f - ax);
    float v = __saturatef(fmaf(ax, -0.5f, 1.0f));
    return fmaf(v * v, fmaf(v, 4.0f, -2.0f), (u * u) * fmaf(u, -2.0f, 1.0f));
}

// cubic value + derivative: dc/dx = sign(x) * (6(u^2 - v^2) + 2(v - u))
__device__ __forceinline__ void cubic_cd(float x, float& c, float& d) {
    float ax = fabsf(x);
    float u = __saturatef(1.0f - ax);
    float v = __saturatef(fmaf(ax, -0.5f, 1.0f));
    float uu = u * u, vv = v * v;
    c = fmaf(vv, fmaf(v, 4.0f, -2.0f), uu * fmaf(u, -2.0f, 1.0f));
    float h = fmaf(uu - vv, 6.0f, 2.0f * (v - u));
    d = copysignf(h, x);
}

__global__ __launch_bounds__(TPB, 8)
void kest_kernel(const float* __restrict__ m,
                 const float* __restrict__ grid,
                 const int*   __restrict__ Wp,
                 const int*   __restrict__ yi,
                 float*       __restrict__ out,
                 int N)
{
    __shared__ __align__(16) float w_s[TPB * KK];  // NORMALIZED weights, output order

    const int t = threadIdx.x;
    const int lane = t & 31;
    const int warp = t >> 5;
    const int n = blockIdx.x * TPB + t;
    const int n_eff = min(n, N - 1);     // all lanes compute (uniform ballot), OOB clamped

    const float m00 = __ldg(m + 0), m01 = __ldg(m + 1), m02 = __ldg(m + 2);
    const float m10 = __ldg(m + 3), m11 = __ldg(m + 4), m12 = __ldg(m + 5);
    const float m20 = __ldg(m + 6), m21 = __ldg(m + 7), m22 = __ldg(m + 8);
    const unsigned W = (unsigned)__ldg(Wp);

    const unsigned p = (unsigned)__ldg(yi + n_eff);
    unsigned pxi, pyi_;
    if ((W & (W - 1u)) == 0u) {          // uniform branch
        const int sh = __ffs((int)W) - 1;
        pxi = p & (W - 1u);
        pyi_ = p >> sh;
    } else {
        pyi_ = p / W;
        pxi = p - pyi_ * W;
    }
    const float px = (float)pxi;
    const float py = (float)pyi_;

    // Analytic central differences of the homography map (exactly equals the
    // reference's (pr-pl), (pb-pt) finite differences, algebraically).
    const float X0 = fmaf(m00, px, fmaf(m01, py, m02));
    const float Y0 = fmaf(m10, px, fmaf(m11, py, m12));
    const float Z0 = fmaf(m20, px, fmaf(m21, py, m22));
    const float Z2 = Z0 * Z0;
    const float da = fmaf(m21, -0.25f * m21, Z2);
    const float db = fmaf(m20, -0.25f * m20, Z2);
    // one reciprocal for both: 1/da = rcp(da*db)*db etc.
    const float rab = __frcp_rn(da * db);
    const float idu = rab * db;
    const float idv = rab * da;

    float du0 = (m01 * Z0 - m21 * X0) * idu;
    float du1 = (m11 * Z0 - m21 * Y0) * idu;
    float dv0 = (m00 * Z0 - m20 * X0) * idv;
    float dv1 = (m10 * Z0 - m20 * Y0) * idv;

    // branch-free |du| >= 1 regularization via rsqrt; keep 1/len for later
    float s  = fmaf(du0, du0, du1 * du1);
    float rs = __frsqrt_rn(s);
    float len = s * rs;
    bool cnd = len < 1.0f;
    float sc = cnd ? rs : 1.0f;
    du0 *= sc; du1 *= sc;
    float rlen_du = cnd ? 1.0f : rs;     // 1/len_du

    float s2  = fmaf(dv0, dv0, dv1 * dv1);
    float rs2 = __frsqrt_rn(s2);
    float len2 = s2 * rs2;
    bool cnd2 = len2 < 1.0f;
    float sc2 = cnd2 ? rs2 : 1.0f;
    dv0 *= sc2; dv1 *= sc2;
    float rlen_dv = cnd2 ? 1.0f : rs2;   // 1/len_dv

    const float det  = du0 * dv1 - du1 * dv0;
    const float rdet = __frcp_rn(det);
    const float ild  = rdet * rlen_du;   // 1/(len_du*det)
    const float ilv  = rdet * rlen_dv;   // 1/(len_dv*det)

    const float Axx = du0 * dv1 * ild - du1 * dv0 * ilv;
    const float Axy = du0 * du1 * (ilv - ild);
    const float Cxx = dv0 * dv1 * (ild - ilv);
    const float Dyy = dv1 * du0 * ilv - dv0 * du1 * ild;

    const float gx = __ldg(grid + n_eff);
    const float gy = __ldg(grid + N + n_eff);
    const float fx = (gx + 0.5f) - floorf(gx + 0.5f);
    const float fy = (gy + 0.5f) - floorf(gy + 0.5f);

    float* wrow = &w_s[t * KK];

    // Taylor validity: max |cross arg| <= 3.5*max(|Axy|,|Cxx|); 1st-order error
    // <= 2.5*thr^2 = 2.5e-4 absolute at thr=1e-2 (tolerance is 1e-3 relative).
    const float cross = fmaxf(fabsf(Axy), fabsf(Cxx)) * 3.5f;
    const bool fast = cross < 1e-2f;
    const bool warp_fast = __all_sync(0xffffffffu, fast);   // uniform path per warp

    if (warp_fast) {
        // ---- fast path: 7x7, 1st-order Taylor in cross terms, factored sum ----
        u64 cx2[3], dx2[3], Cv2[3];
        float cx6, dx6, Cv6;
        float Scx, Sdx, Scxc, Sdxc;
        {
            float c0, d0, c1, d1, v0, v1;
            cubic_cd(Axx * (fx + 2.5f), c0, d0);
            cubic_cd(Axx * (fx + 1.5f), c1, d1);
            v0 = Cxx * (fx + 2.5f); v1 = Cxx * (fx + 1.5f);
            cx2[0] = pk2(c0, c1); dx2[0] = pk2(d0, d1); Cv2[0] = pk2(v0, v1);
            Scx = c0 + c1; Sdx = d0 + d1;
            Scxc = fmaf(c0, v0, c1 * v1);
            Sdxc = fmaf(d0, v0, d1 * v1);

            cubic_cd(Axx * (fx + 0.5f), c0, d0);
            cubic_cd(Axx * (fx - 0.5f), c1, d1);
            v0 = Cxx * (fx + 0.5f); v1 = Cxx * (fx - 0.5f);
            cx2[1] = pk2(c0, c1); dx2[1] = pk2(d0, d1); Cv2[1] = pk2(v0, v1);
            Scx += c0 + c1; Sdx += d0 + d1;
            Scxc = fmaf(c0, v0, fmaf(c1, v1, Scxc));
            Sdxc = fmaf(d0, v0, fmaf(d1, v1, Sdxc));

            cubic_cd(Axx * (fx - 1.5f), c0, d0);
            cubic_cd(Axx * (fx - 2.5f), c1, d1);
            v0 = Cxx * (fx - 1.5f); v1 = Cxx * (fx - 2.5f);
            cx2[2] = pk2(c0, c1); dx2[2] = pk2(d0, d1); Cv2[2] = pk2(v0, v1);
            Scx += c0 + c1; Sdx += d0 + d1;
            Scxc = fmaf(c0, v0, fmaf(c1, v1, Scxc));
            Sdxc = fmaf(d0, v0, fmaf(d1, v1, Sdxc));

            cubic_cd(Axx * (fx - 3.5f), cx6, dx6);
            Cv6 = Cxx * (fx - 3.5f);
            Scx += cx6; Sdx += dx6;
            Scxc = fmaf(cx6, Cv6, Scxc);
            Sdxc = fmaf(dx6, Cv6, Sdxc);
        }

        // factored sum over y (transient)
        float sum = 0.0f;
        #pragma unroll
        for (int k = 0; k < KS; k++) {
            float wyk = fy + 2.5f - (float)k;
            float cy, dy;
            cubic_cd(Dyy * wyk, cy, dy);
            float By = Axy * wyk;
            sum = fmaf(cy, fmaf(By, Sdx, Scx),
                  fmaf(dy, fmaf(By, Sdxc, Scxc), sum));
        }
        const float inv = __frcp_rn(sum);

        // element loop: recompute y terms per row, write normalized weights
        #pragma unroll
        for (int ky = 0; ky < KS; ky++) {
            float wyk = fy + 2.5f - (float)ky;
            float cy, dy;
            cubic_cd(Dyy * wyk, cy, dy);
            float By = Axy * wyk;
            cy *= inv; dy *= inv;
            u64 B2  = pk2(By, By);
            u64 cy2 = pk2(cy, cy);
            u64 dy2 = pk2(dy, dy);
            float* r = wrow + ky * KS;
            #pragma unroll
            for (int j = 0; j < 3; j++) {
                u64 a  = fma2(B2, dx2[j], cx2[j]);
                u64 b  = fma2(Cv2[j], dy2, cy2);
                u64 w2 = mul2(a, b);
                float wl, wh; unpk2(w2, wl, wh);
                r[2*j]   = wl;
                r[2*j+1] = wh;
            }
            r[6] = fmaf(By, dx6, cx6) * fmaf(Cv6, dy, cy);
        }
    } else {
        // ---- exact path (whole warp): full 7x7 evaluation ----
        float A[KS], Cc[KS];
        #pragma unroll
        for (int k = 0; k < KS; k++) {
            float wxk = fx + 2.5f - (float)k;
            A[k] = Axx * wxk;
            Cc[k] = Cxx * wxk;
        }
        float sum0 = 0.0f, sum1 = 0.0f;
        #pragma unroll
        for (int ky = 0; ky < KS; ky++) {
            float wyk = fy + 2.5f - (float)ky;
            float Bk = Axy * wyk;
            float Dk = Dyy * wyk;
            #pragma unroll
            for (int kx = 0; kx < KS; kx++) {
                float w = cubic_w(A[kx] + Bk) * cubic_w(Cc[kx] + Dk);
                if (kx & 1) sum1 += w; else sum0 += w;
                wrow[ky * KS + kx] = w;
            }
        }
        const float inv = __frcp_rn(sum0 + sum1);
        #pragma unroll
        for (int j = 0; j < KK; j++) wrow[j] *= inv;
    }

    // ---- per-warp write-out: bulk async copy of this warp's 32 rows ----
    __syncwarp();
    const long long blockBase = (long long)blockIdx.x * (TPB * KK);
    const int warpPixBase = blockIdx.x * TPB + warp * 32;
    const int pix = min(32, N - warpPixBase);
    if (pix == 32) {
        if (lane == 0) {
            unsigned saddr = (unsigned)__cvta_generic_to_shared(w_s + warp * 32 * KK);
            asm volatile("fence.proxy.async.shared::cta;" ::: "memory");
            asm volatile("cp.async.bulk.global.shared::cta.bulk_group [%0], [%1], %2;"
                         :: "l"(out + blockBase + warp * 32 * KK), "r"(saddr),
                            "r"((unsigned)(32 * KK * 4))
                         : "memory");
            asm volatile("cp.async.bulk.commit_group;" ::: "memory");
            asm volatile("cp.async.bulk.wait_group 0;" ::: "memory");
        }
    } else if (pix > 0) {
        const int cnt = pix * KK;
        const int off = warp * 32 * KK;
        for (int i = lane; i < cnt; i += 32) out[blockBase + off + i] = w_s[off + i];
    }
}

extern "C" void kernel_launch(void* const* d_in, const int* in_sizes, int n_in,
                              void* d_out, int out_size) {
    // metadata order: m_inverse (9), grid (2N), H (1), W (1), yi (N)
    const float* m    = (const float*)d_in[0];
    const float* grid = (const float*)d_in[1];
    const int*   Wp   = (const int*)d_in[3];
    const int*   yi   = (const int*)d_in[4];
    float* out = (float*)d_out;

    const int N = in_sizes[4];
    const int blocks = (N + TPB - 1) / TPB;
    kest_kernel<<<blocks, TPB>>>(m, grid, Wp, yi, out, N);
}